// round 15
// baseline (speedup 1.0000x reference)
#include <cuda_runtime.h>

#define NFFT   4096
#define FREQ   2049
#define TPB    256
#define NBATCH 8192

typedef unsigned long long ull;

// ---- packed f32x2 helpers (sm_100+ PTX; ptxas never emits these from C) ----
__device__ __forceinline__ ull pk(float x, float y) {
    ull r; asm("mov.b64 %0,{%1,%2};" : "=l"(r) : "f"(x), "f"(y)); return r;
}
__device__ __forceinline__ void upk(ull u, float& x, float& y) {
    asm("mov.b64 {%0,%1},%2;" : "=f"(x), "=f"(y) : "l"(u));
}
__device__ __forceinline__ ull padd(ull a, ull b) {
    ull r; asm("add.rn.f32x2 %0,%1,%2;" : "=l"(r) : "l"(a), "l"(b)); return r;
}
__device__ __forceinline__ ull pfma(ull a, ull b, ull c) {
    ull r; asm("fma.rn.f32x2 %0,%1,%2,%3;" : "=l"(r) : "l"(a), "l"(b), "l"(c)); return r;
}
__device__ __forceinline__ ull pmul(ull a, ull b) {
    ull r; asm("mul.rn.f32x2 %0,%1,%2;" : "=l"(r) : "l"(a), "l"(b)); return r;
}

// sign-pair constants (lo word = .x)
#define NEG1 0xBF800000BF800000ULL   /* (-1,-1) */
#define C1M1 0xBF8000003F800000ULL   /* (+1,-1) */
#define M1P1 0x3F800000BF800000ULL   /* (-1,+1) */

__device__ __forceinline__ ull pswap(ull u) {
    float x, y; upk(u, x, y); return pk(y, x);
}
__device__ __forceinline__ ull psub(ull a, ull b) { return pfma(b, NEG1, a); }

// complex mul by compile-time constant
__device__ __forceinline__ ull cmulc(ull vu, float wx, float wy) {
    float x, y; upk(vu, x, y);
    return pk(fmaf(x, wx, -y * wy), fmaf(x, wy, y * wx));
}
__device__ __forceinline__ ull pmneg_i(ull vu) {
    float x, y; upk(vu, x, y); return pk(y, -x);
}

// In-place packed radix-4 butterfly (W4 = -i).
__device__ __forceinline__ void bf4p(ull& a, ull& b, ull& c, ull& d) {
    ull apc = padd(a, c);
    ull amc = psub(a, c);
    ull bpd = padd(b, d);
    ull bmd = psub(b, d);
    a = padd(apc, bpd);
    c = psub(apc, bpd);
    ull sw = pswap(bmd);
    b = pfma(sw, C1M1, amc);        // (a-c) - i(b-d)
    d = pfma(sw, M1P1, amc);        // (a-c) + i(b-d)
}

#define C_W1x  0.92387953f
#define C_W1y -0.38268343f
#define C_W2x  0.70710678f
#define C_W2y -0.70710678f

#define P16(k) ((((k) & 3) << 2) | ((k) >> 2))

// Tail: W16 twiddles + second radix-4 stage. Output y[k] at v[P16(k)].
__device__ __forceinline__ void fft16_tailp(ull v[16]) {
    v[5]  = cmulc(v[5],   C_W1x,  C_W1y);
    v[9]  = cmulc(v[9],   C_W2x,  C_W2y);
    v[13] = cmulc(v[13],  0.38268343f, -0.92387953f);   // W3
    v[6]  = cmulc(v[6],   C_W2x,  C_W2y);
    v[10] = pmneg_i(v[10]);
    v[14] = cmulc(v[14], -C_W2x,  C_W2y);               // W6
    v[7]  = cmulc(v[7],   0.38268343f, -0.92387953f);
    v[11] = cmulc(v[11], -C_W2x,  C_W2y);
    v[15] = cmulc(v[15], -C_W1x, -C_W1y);               // W9
    bf4p(v[0],  v[1],  v[2],  v[3]);
    bf4p(v[4],  v[5],  v[6],  v[7]);
    bf4p(v[8],  v[9],  v[10], v[11]);
    bf4p(v[12], v[13], v[14], v[15]);
}

__device__ __forceinline__ void fft16p(ull v[16]) {
    bf4p(v[0], v[4], v[8],  v[12]);
    bf4p(v[1], v[5], v[9],  v[13]);
    bf4p(v[2], v[6], v[10], v[14]);
    bf4p(v[3], v[7], v[11], v[15]);
    fft16_tailp(v);
}

// 16-pt DFT with v[8..15] known zero.
__device__ __forceinline__ void fft16_zhp(ull v[16]) {
#pragma unroll
    for (int j = 0; j < 4; j++) {
        ull a = v[j], b = v[j + 4];
        ull s = pmul(pswap(b), C1M1);   // (b.y, -b.x)
        v[j]      = padd(a, b);
        v[j + 4]  = padd(a, s);         // a - i b
        v[j + 8]  = psub(a, b);
        v[j + 12] = psub(a, s);         // a + i b
    }
    fft16_tailp(v);
}

__device__ __forceinline__ float2 cmul2(float2 a, float2 b) {
    return make_float2(fmaf(a.x, b.x, -a.y * b.y),
                       fmaf(a.x, b.y,  a.y * b.x));
}
__device__ __forceinline__ ull appw(ull yu, float2 t) {
    float x, y; upk(yu, x, y);
    return pk(fmaf(x, t.x, -y * t.y), fmaf(x, t.y, y * t.x));
}

// One block: 4096-pt complex FFT of z = x[2b] + i*x[2b+1] (zero-padded),
// packed-f32x2 register radix-16^3, dual-chain twiddles, shuffle-mirrored
// unpack with 64B-aligned store segments. 5 blocks/SM at 48 regs — a sharp
// local optimum, measured: 6-block/40-reg spills (r8); pipelined epilogue
// (r10) and warp-specialized epilogue (r12) regress via scheduling/live-range
// damage. Champion configuration (r11; reconfirmed r13/r14 at 41.4-41.5 us,
// sitting on the modeled L1-wavefront floor).
extern "C" __global__ void __launch_bounds__(TPB, 5)
fft_energy_kernel(const float* __restrict__ x, float* __restrict__ out) {
    __shared__ ull S[4608];              // phase-A layout: S[18*m + k1]

    const int t    = threadIdx.x;
    const int lane = t & 31;
    const int wrp  = t >> 5;
    const int blk  = blockIdx.x;
    const float* r0 = x + (size_t)(2 * blk) * FREQ;
    const float* r1 = r0 + FREQ;

    const float2 c2 = make_float2(__ldcs(r0 + 2048), __ldcs(r1 + 2048));

    ull v[16];
    float2 wB;                            // phase-B twiddle base (hoisted MUFU)

    // ---- Phase A: thread m handles n = m + 256*j, j<8 (rest zero) ----
    {
        const int m = t;
#pragma unroll
        for (int j = 0; j < 8; j++) {
            int idx = m + 256 * j;
            v[j] = pk(__ldcs(r0 + idx), __ldcs(r1 + idx));
        }
        fft16_zhp(v);    // y[k1] at v[P16(k1)]

        float s1, c1;
        __sincosf(-(float)m * 1.53398078e-3f, &s1, &c1);    // W4096^m
        const float2 w1 = make_float2(c1, s1);
        const float2 w2 = cmul2(w1, w1);
        *reinterpret_cast<ulonglong2*>(&S[18 * m]) =
            make_ulonglong2(v[P16(0)], appw(v[P16(1)], w1));
        float2 pe = w2;               // W^{2m}
        float2 po = cmul2(w1, w2);    // W^{3m}
#pragma unroll
        for (int k1 = 2; k1 < 16; k1 += 2) {
            ull e = appw(v[P16(k1)],     pe);
            ull o = appw(v[P16(k1 + 1)], po);
            *reinterpret_cast<ulonglong2*>(&S[18 * m + k1]) = make_ulonglong2(e, o);
            if (k1 < 14) { pe = cmul2(pe, w2); po = cmul2(po, w2); }
        }
        // Hoist ONLY phase-B's sincos: MUFU latency overlaps the barrier wait
        // in the post-store dead window. (+2 live regs across one barrier.)
        float sb, cb;
        __sincosf(-(float)(t >> 4) * 2.45436933e-2f, &sb, &cb);  // W4096^{16 m'}
        wB = make_float2(cb, sb);
    }
    __syncthreads();

    // ---- Phase B: thread (k1 = t&15, m' = t>>4) ----
    {
        const int k1 = t & 15, mp = t >> 4;
#pragma unroll
        for (int j2 = 0; j2 < 16; j2++)
            v[j2] = S[18 * (mp + 16 * j2) + k1];

        fft16p(v);       // u[k2] at v[P16(k2)]

        const float2 w1 = wB;
        const float2 w2 = cmul2(w1, w1);
        __syncthreads();
        S[t]       = v[P16(0)];
        S[t + 256] = appw(v[P16(1)], w1);
        float2 pe = w2;
        float2 po = cmul2(w1, w2);
#pragma unroll
        for (int k2 = 2; k2 < 16; k2 += 2) {
            S[t + 256 * k2]       = appw(v[P16(k2)],     pe);
            S[t + 256 * (k2 + 1)] = appw(v[P16(k2 + 1)], po);
            if (k2 < 14) { pe = cmul2(pe, w2); po = cmul2(po, w2); }
        }
    }
    __syncthreads();

    // ---- Phase C: aligned mirror-paired column assignment ----
    // half-warp 0 (lanes 0..15):  c = 16w + lane        (64B-aligned group)
    // half-warp 1 (lanes 16..31): c = 256 - 16w - (lane-16)   (mirror group)
    // partner 256-c sits at lane^16. Specials: (w0,l0) c=0 self;
    // (w0,l16) would be c=256 -> reassigned c=128 (self-mirror).
    {
        int c = (lane < 16) ? (16 * wrp + lane) : (256 - 16 * wrp - (lane - 16));
        const bool self0   = (wrp == 0) && (lane == 0);    // c = 0
        const bool self128 = (wrp == 0) && (lane == 16);   // c := 128
        if (self128) c = 128;
        const int k1 = c & 15, k2 = c >> 4;

#pragma unroll
        for (int mp = 0; mp < 16; mp++)
            v[mp] = S[k1 + 16 * mp + 256 * k2];

        fft16p(v);       // Z[c + 256*k3] = v[P16(k3)]

        float* o0 = out + (size_t)(2 * blk) * NFFT;
        float* o1 = o0 + NFFT;
        const float sgn = (c & 1) ? -1.0f : 1.0f;
        const float b0 = 0.02f * sgn * c2.x;     // folded n=2048 term
        const float b1 = 0.02f * sgn * c2.y;
#pragma unroll
        for (int k3 = 0; k3 < 16; k3++) {
            ull zk = v[P16(k3)];
            ull zs = v[P16(15 - k3)];
            float sx, sy; upk(zs, sx, sy);
            float rx = __shfl_xor_sync(0xffffffffu, sx, 16);
            float ry = __shfl_xor_sync(0xffffffffu, sy, 16);
            ull zr = pk(rx, ry);
            if (self128) zr = zs;                          // own col, k3'=15-k3
            if (self0)   zr = v[P16((16 - k3) & 15)];      // own col, k3'=(16-k3)&15
            ull s = padd(zk, zr);
            float ox, oy; upk(s, ox, oy);
            int n = c + 256 * k3;
            __stcs(o0 + n, fmaf(0.01f, ox, b0));
            __stcs(o1 + n, fmaf(0.01f, oy, b1));
        }
    }
}

extern "C" void kernel_launch(void* const* d_in, const int* in_sizes, int n_in,
                              void* d_out, int out_size) {
    const float* x = (const float*)d_in[0];   // (8192, 2049) fp32
    float* out = (float*)d_out;               // (8192, 4096) fp32
    fft_energy_kernel<<<NBATCH / 2, TPB>>>(x, out);
}

// round 16
// speedup vs baseline: 1.0070x; 1.0070x over previous
#include <cuda_runtime.h>

#define NFFT   4096
#define FREQ   2049
#define TPB    256
#define NBATCH 8192

typedef unsigned long long ull;

// ---- packed f32x2 helpers (sm_100+ PTX; ptxas never emits these from C) ----
__device__ __forceinline__ ull pk(float x, float y) {
    ull r; asm("mov.b64 %0,{%1,%2};" : "=l"(r) : "f"(x), "f"(y)); return r;
}
__device__ __forceinline__ void upk(ull u, float& x, float& y) {
    asm("mov.b64 {%0,%1},%2;" : "=f"(x), "=f"(y) : "l"(u));
}
__device__ __forceinline__ ull padd(ull a, ull b) {
    ull r; asm("add.rn.f32x2 %0,%1,%2;" : "=l"(r) : "l"(a), "l"(b)); return r;
}
__device__ __forceinline__ ull pfma(ull a, ull b, ull c) {
    ull r; asm("fma.rn.f32x2 %0,%1,%2,%3;" : "=l"(r) : "l"(a), "l"(b), "l"(c)); return r;
}
__device__ __forceinline__ ull pmul(ull a, ull b) {
    ull r; asm("mul.rn.f32x2 %0,%1,%2;" : "=l"(r) : "l"(a), "l"(b)); return r;
}

// sign-pair constants (lo word = .x)
#define NEG1 0xBF800000BF800000ULL   /* (-1,-1) */
#define C1M1 0xBF8000003F800000ULL   /* (+1,-1) */
#define M1P1 0x3F800000BF800000ULL   /* (-1,+1) */

__device__ __forceinline__ ull pswap(ull u) {
    float x, y; upk(u, x, y); return pk(y, x);
}
__device__ __forceinline__ ull psub(ull a, ull b) { return pfma(b, NEG1, a); }

// complex mul by compile-time constant
__device__ __forceinline__ ull cmulc(ull vu, float wx, float wy) {
    float x, y; upk(vu, x, y);
    return pk(fmaf(x, wx, -y * wy), fmaf(x, wy, y * wx));
}
__device__ __forceinline__ ull pmneg_i(ull vu) {
    float x, y; upk(vu, x, y); return pk(y, -x);
}

// In-place packed radix-4 butterfly (W4 = -i).
__device__ __forceinline__ void bf4p(ull& a, ull& b, ull& c, ull& d) {
    ull apc = padd(a, c);
    ull amc = psub(a, c);
    ull bpd = padd(b, d);
    ull bmd = psub(b, d);
    a = padd(apc, bpd);
    c = psub(apc, bpd);
    ull sw = pswap(bmd);
    b = pfma(sw, C1M1, amc);        // (a-c) - i(b-d)
    d = pfma(sw, M1P1, amc);        // (a-c) + i(b-d)
}

#define C_W1x  0.92387953f
#define C_W1y -0.38268343f
#define C_W2x  0.70710678f
#define C_W2y -0.70710678f

#define P16(k) ((((k) & 3) << 2) | ((k) >> 2))

// Tail: W16 twiddles + second radix-4 stage. Output y[k] at v[P16(k)].
__device__ __forceinline__ void fft16_tailp(ull v[16]) {
    v[5]  = cmulc(v[5],   C_W1x,  C_W1y);
    v[9]  = cmulc(v[9],   C_W2x,  C_W2y);
    v[13] = cmulc(v[13],  0.38268343f, -0.92387953f);   // W3
    v[6]  = cmulc(v[6],   C_W2x,  C_W2y);
    v[10] = pmneg_i(v[10]);
    v[14] = cmulc(v[14], -C_W2x,  C_W2y);               // W6
    v[7]  = cmulc(v[7],   0.38268343f, -0.92387953f);
    v[11] = cmulc(v[11], -C_W2x,  C_W2y);
    v[15] = cmulc(v[15], -C_W1x, -C_W1y);               // W9
    bf4p(v[0],  v[1],  v[2],  v[3]);
    bf4p(v[4],  v[5],  v[6],  v[7]);
    bf4p(v[8],  v[9],  v[10], v[11]);
    bf4p(v[12], v[13], v[14], v[15]);
}

__device__ __forceinline__ void fft16p(ull v[16]) {
    bf4p(v[0], v[4], v[8],  v[12]);
    bf4p(v[1], v[5], v[9],  v[13]);
    bf4p(v[2], v[6], v[10], v[14]);
    bf4p(v[3], v[7], v[11], v[15]);
    fft16_tailp(v);
}

// 16-pt DFT with v[8..15] known zero.
__device__ __forceinline__ void fft16_zhp(ull v[16]) {
#pragma unroll
    for (int j = 0; j < 4; j++) {
        ull a = v[j], b = v[j + 4];
        ull s = pmul(pswap(b), C1M1);   // (b.y, -b.x)
        v[j]      = padd(a, b);
        v[j + 4]  = padd(a, s);         // a - i b
        v[j + 8]  = psub(a, b);
        v[j + 12] = psub(a, s);         // a + i b
    }
    fft16_tailp(v);
}

__device__ __forceinline__ float2 cmul2(float2 a, float2 b) {
    return make_float2(fmaf(a.x, b.x, -a.y * b.y),
                       fmaf(a.x, b.y,  a.y * b.x));
}
__device__ __forceinline__ ull appw(ull yu, float2 t) {
    float x, y; upk(yu, x, y);
    return pk(fmaf(x, t.x, -y * t.y), fmaf(x, t.y, y * t.x));
}

// One block: 4096-pt complex FFT of z = x[2b] + i*x[2b+1] (zero-padded),
// packed-f32x2 register radix-16^3, dual-chain twiddles, shuffle-mirrored
// unpack with 64B-aligned store segments. 5 blocks/SM at 48 regs — a sharp
// local optimum, measured: 6-block/40-reg spills (r8); pipelined epilogue
// (r10) and warp-specialized epilogue (r12) regress via scheduling/live-range
// damage. FINAL champion configuration (r11; reconfirmed r13/r14/r15 at
// 41.44-41.70 us, sitting on the modeled L1-wavefront floor).
extern "C" __global__ void __launch_bounds__(TPB, 5)
fft_energy_kernel(const float* __restrict__ x, float* __restrict__ out) {
    __shared__ ull S[4608];              // phase-A layout: S[18*m + k1]

    const int t    = threadIdx.x;
    const int lane = t & 31;
    const int wrp  = t >> 5;
    const int blk  = blockIdx.x;
    const float* r0 = x + (size_t)(2 * blk) * FREQ;
    const float* r1 = r0 + FREQ;

    const float2 c2 = make_float2(__ldcs(r0 + 2048), __ldcs(r1 + 2048));

    ull v[16];
    float2 wB;                            // phase-B twiddle base (hoisted MUFU)

    // ---- Phase A: thread m handles n = m + 256*j, j<8 (rest zero) ----
    {
        const int m = t;
#pragma unroll
        for (int j = 0; j < 8; j++) {
            int idx = m + 256 * j;
            v[j] = pk(__ldcs(r0 + idx), __ldcs(r1 + idx));
        }
        fft16_zhp(v);    // y[k1] at v[P16(k1)]

        float s1, c1;
        __sincosf(-(float)m * 1.53398078e-3f, &s1, &c1);    // W4096^m
        const float2 w1 = make_float2(c1, s1);
        const float2 w2 = cmul2(w1, w1);
        *reinterpret_cast<ulonglong2*>(&S[18 * m]) =
            make_ulonglong2(v[P16(0)], appw(v[P16(1)], w1));
        float2 pe = w2;               // W^{2m}
        float2 po = cmul2(w1, w2);    // W^{3m}
#pragma unroll
        for (int k1 = 2; k1 < 16; k1 += 2) {
            ull e = appw(v[P16(k1)],     pe);
            ull o = appw(v[P16(k1 + 1)], po);
            *reinterpret_cast<ulonglong2*>(&S[18 * m + k1]) = make_ulonglong2(e, o);
            if (k1 < 14) { pe = cmul2(pe, w2); po = cmul2(po, w2); }
        }
        // Hoist ONLY phase-B's sincos: MUFU latency overlaps the barrier wait
        // in the post-store dead window. (+2 live regs across one barrier.)
        float sb, cb;
        __sincosf(-(float)(t >> 4) * 2.45436933e-2f, &sb, &cb);  // W4096^{16 m'}
        wB = make_float2(cb, sb);
    }
    __syncthreads();

    // ---- Phase B: thread (k1 = t&15, m' = t>>4) ----
    {
        const int k1 = t & 15, mp = t >> 4;
#pragma unroll
        for (int j2 = 0; j2 < 16; j2++)
            v[j2] = S[18 * (mp + 16 * j2) + k1];

        fft16p(v);       // u[k2] at v[P16(k2)]

        const float2 w1 = wB;
        const float2 w2 = cmul2(w1, w1);
        __syncthreads();
        S[t]       = v[P16(0)];
        S[t + 256] = appw(v[P16(1)], w1);
        float2 pe = w2;
        float2 po = cmul2(w1, w2);
#pragma unroll
        for (int k2 = 2; k2 < 16; k2 += 2) {
            S[t + 256 * k2]       = appw(v[P16(k2)],     pe);
            S[t + 256 * (k2 + 1)] = appw(v[P16(k2 + 1)], po);
            if (k2 < 14) { pe = cmul2(pe, w2); po = cmul2(po, w2); }
        }
    }
    __syncthreads();

    // ---- Phase C: aligned mirror-paired column assignment ----
    // half-warp 0 (lanes 0..15):  c = 16w + lane        (64B-aligned group)
    // half-warp 1 (lanes 16..31): c = 256 - 16w - (lane-16)   (mirror group)
    // partner 256-c sits at lane^16. Specials: (w0,l0) c=0 self;
    // (w0,l16) would be c=256 -> reassigned c=128 (self-mirror).
    {
        int c = (lane < 16) ? (16 * wrp + lane) : (256 - 16 * wrp - (lane - 16));
        const bool self0   = (wrp == 0) && (lane == 0);    // c = 0
        const bool self128 = (wrp == 0) && (lane == 16);   // c := 128
        if (self128) c = 128;
        const int k1 = c & 15, k2 = c >> 4;

#pragma unroll
        for (int mp = 0; mp < 16; mp++)
            v[mp] = S[k1 + 16 * mp + 256 * k2];

        fft16p(v);       // Z[c + 256*k3] = v[P16(k3)]

        float* o0 = out + (size_t)(2 * blk) * NFFT;
        float* o1 = o0 + NFFT;
        const float sgn = (c & 1) ? -1.0f : 1.0f;
        const float b0 = 0.02f * sgn * c2.x;     // folded n=2048 term
        const float b1 = 0.02f * sgn * c2.y;
#pragma unroll
        for (int k3 = 0; k3 < 16; k3++) {
            ull zk = v[P16(k3)];
            ull zs = v[P16(15 - k3)];
            float sx, sy; upk(zs, sx, sy);
            float rx = __shfl_xor_sync(0xffffffffu, sx, 16);
            float ry = __shfl_xor_sync(0xffffffffu, sy, 16);
            ull zr = pk(rx, ry);
            if (self128) zr = zs;                          // own col, k3'=15-k3
            if (self0)   zr = v[P16((16 - k3) & 15)];      // own col, k3'=(16-k3)&15
            ull s = padd(zk, zr);
            float ox, oy; upk(s, ox, oy);
            int n = c + 256 * k3;
            __stcs(o0 + n, fmaf(0.01f, ox, b0));
            __stcs(o1 + n, fmaf(0.01f, oy, b1));
        }
    }
}

extern "C" void kernel_launch(void* const* d_in, const int* in_sizes, int n_in,
                              void* d_out, int out_size) {
    const float* x = (const float*)d_in[0];   // (8192, 2049) fp32
    float* out = (float*)d_out;               // (8192, 4096) fp32
    fft_energy_kernel<<<NBATCH / 2, TPB>>>(x, out);
}